// round 15
// baseline (speedup 1.0000x reference)
#include <cuda_runtime.h>
#include <math.h>

#define MAXC 4096
#define NREP 16

// Scratch (device globals: zero-initialized at load; every kernel_launch
// leaves them zeroed again -> no zero kernel needed).
// g_mom[rep][cluster*16]: cnt,sx,sy,sz | sxx,sxy,sxz,syy | syz,szz,pad...
__device__ __align__(128) float g_mom[NREP][MAXC * 16];   // 4 MB
__device__ float4 g_ctr[MAXC];       // cx, cy, cz, 0
__device__ float4 g_vd[MAXC];        // v0x, v0y, v0z, dirwt
__device__ __align__(128) float g_sc[NREP][MAXC];         // replicated sign accum
__device__ float  g_cnt[MAXC];       // merged counts (for fin)

// ---------------------------------------------------------------------------
// v4 + v4 + v2 global f32 reductions into one of NREP table replicas.
// (Proven minimum: red.f32 is capped at 128-bit vectors on sm_103.)
__device__ __forceinline__ void mom_red(int rep, int c, float x, float y, float z) {
    float* base = &g_mom[rep][c * 16];
    size_t g0 = __cvta_generic_to_global(base);
    size_t g1 = __cvta_generic_to_global(base + 4);
    size_t g2 = __cvta_generic_to_global(base + 8);
    asm volatile("red.global.add.v4.f32 [%0], {%1,%2,%3,%4};"
                 :: "l"(g0), "f"(1.0f), "f"(x), "f"(y), "f"(z) : "memory");
    asm volatile("red.global.add.v4.f32 [%0], {%1,%2,%3,%4};"
                 :: "l"(g1), "f"(x * x), "f"(x * y), "f"(x * z), "f"(y * y) : "memory");
    asm volatile("red.global.add.v2.f32 [%0], {%1,%2};"
                 :: "l"(g2), "f"(y * z), "f"(z * z) : "memory");
}

// Pass 1: per-cluster moments, 4 records/thread, coalesced LDG.128,
// replica chosen per warp to cut per-address contention 16x.
__global__ void moments_kernel(const float* __restrict__ data,
                               const int* __restrict__ cid, int n, int nquad) {
    int t = blockIdx.x * blockDim.x + threadIdx.x;
    int rep = (blockIdx.x * 8 + (threadIdx.x >> 5)) & (NREP - 1);
    if (t < nquad) {
        const float4* d4 = (const float4*)data;
        float4 f0 = d4[t * 5 + 0];
        float4 f1 = d4[t * 5 + 1];
        float4 f2 = d4[t * 5 + 2];
        float4 f3 = d4[t * 5 + 3];
        float4 f4 = d4[t * 5 + 4];
        int4 c4 = ((const int4*)cid)[t];
        mom_red(rep, c4.x, f0.x, f0.y, f0.z);
        mom_red(rep, c4.y, f1.y, f1.z, f1.w);
        mom_red(rep, c4.z, f2.z, f2.w, f3.x);
        mom_red(rep, c4.w, f3.w, f4.x, f4.y);
    }
    if (t == 0) {
        for (int i = nquad * 4; i < n; i++) {
            const float* p = data + (size_t)i * 5;
            mom_red(0, cid[i], p[0], p[1], p[2]);
        }
    }
}

// ---------------------------------------------------------------------------
// Pass 2: merge replicas (then re-zero them for the next launch), center,
// cov, analytic 3x3 eigendecomposition (fp64), B = cov / w2, dirwt, v0.
__global__ void eig_kernel(float* __restrict__ out, int C) {
    int c = blockIdx.x * blockDim.x + threadIdx.x;
    if (c >= C) return;

    float s0 = 0, s1 = 0, s2 = 0, s3 = 0, s4 = 0, s5 = 0, s6 = 0, s7 = 0, s8 = 0, s9 = 0;
    const float4 zz = make_float4(0.0f, 0.0f, 0.0f, 0.0f);
    #pragma unroll 4
    for (int r = 0; r < NREP; r++) {
        float4* m4 = (float4*)&g_mom[r][c * 16];
        float4 a = m4[0], b = m4[1], d = m4[2];
        s0 += a.x; s1 += a.y; s2 += a.z; s3 += a.w;
        s4 += b.x; s5 += b.y; s6 += b.z; s7 += b.w;
        s8 += d.x; s9 += d.y;
        m4[0] = zz; m4[1] = zz; m4[2] = zz;   // self-clean for next launch
    }

    float cnt = s0;
    float safe = fmaxf(cnt, 1.0f);
    float cx = s1 / safe, cy = s2 / safe, cz = s3 / safe;

    double dcnt = (double)cnt;
    double a00 = (double)s4 - dcnt * (double)cx * (double)cx;
    double a01 = (double)s5 - dcnt * (double)cx * (double)cy;
    double a02 = (double)s6 - dcnt * (double)cx * (double)cz;
    double a11 = (double)s7 - dcnt * (double)cy * (double)cy;
    double a12 = (double)s8 - dcnt * (double)cy * (double)cz;
    double a22 = (double)s9 - dcnt * (double)cz * (double)cz;

    // eigenvalues (ascending), trig method
    double p1 = a01 * a01 + a02 * a02 + a12 * a12;
    double q  = (a00 + a11 + a22) / 3.0;
    double d0 = a00 - q, d1 = a11 - q, d2 = a22 - q;
    double p2 = d0 * d0 + d1 * d1 + d2 * d2 + 2.0 * p1;
    double w1, w2;
    if (p2 <= 0.0) {
        w1 = w2 = q;
    } else {
        double p = sqrt(p2 / 6.0);
        double ip = 1.0 / p;
        double b00 = d0 * ip, b01 = a01 * ip, b02 = a02 * ip;
        double b11 = d1 * ip, b12 = a12 * ip, b22 = d2 * ip;
        double detB = b00 * (b11 * b22 - b12 * b12)
                    - b01 * (b01 * b22 - b12 * b02)
                    + b02 * (b01 * b12 - b11 * b02);
        double rr = 0.5 * detB;
        rr = fmin(1.0, fmax(-1.0, rr));
        double phi = acos(rr) / 3.0;
        w2 = q + 2.0 * p * cos(phi);
        double w0 = q + 2.0 * p * cos(phi + 2.0943951023931953);
        w1 = 3.0 * q - w0 - w2;
    }

    float dirwt = (w2 > 0.0) ? (float)(1.0 - w1 / w2) : 0.0f;

    // principal eigenvector: cross products of rows of (A - w2*I)
    double m00 = a00 - w2, m11 = a11 - w2, m22 = a22 - w2;
    double c0x = a01 * a12 - a02 * m11, c0y = a02 * a01 - m00 * a12, c0z = m00 * m11 - a01 * a01;
    double c1x = a01 * m22 - a02 * a12, c1y = a02 * a02 - m00 * m22, c1z = m00 * a12 - a01 * a02;
    double c2x = m11 * m22 - a12 * a12, c2y = a12 * a02 - a01 * m22, c2z = a01 * a12 - m11 * a02;
    double n0 = c0x * c0x + c0y * c0y + c0z * c0z;
    double n1 = c1x * c1x + c1y * c1y + c1z * c1z;
    double n2 = c2x * c2x + c2y * c2y + c2z * c2z;
    double vx, vy, vz, nn;
    if (n0 >= n1 && n0 >= n2)      { vx = c0x; vy = c0y; vz = c0z; nn = n0; }
    else if (n1 >= n2)             { vx = c1x; vy = c1y; vz = c1z; nn = n1; }
    else                           { vx = c2x; vy = c2y; vz = c2z; nn = n2; }
    if (nn > 1e-300) {
        double inv = rsqrt(nn);
        vx *= inv; vy *= inv; vz *= inv;
    } else {
        vx = vy = vz = 0.0;
    }

    bool small = cnt < 2.0f;
    double denom = (fabs(w2) > 1e-12) ? w2 : 1.0;
    double ib = 1.0 / denom;

    float* o = out + (size_t)c * 16;
    o[0] = cx; o[1] = cy; o[2] = cz;
    if (small) {
        #pragma unroll
        for (int k = 3; k < 12; k++) o[k] = 0.0f;
    } else {
        o[3]  = (float)(a00 * ib); o[4]  = (float)(a01 * ib); o[5]  = (float)(a02 * ib);
        o[6]  = (float)(a01 * ib); o[7]  = (float)(a11 * ib); o[8]  = (float)(a12 * ib);
        o[9]  = (float)(a02 * ib); o[10] = (float)(a12 * ib); o[11] = (float)(a22 * ib);
    }
    o[15] = cnt;

    g_cnt[c] = cnt;
    g_ctr[c] = make_float4(cx, cy, cz, 0.0f);
    g_vd[c]  = make_float4((float)vx, (float)vy, (float)vz, dirwt);
}

// ---------------------------------------------------------------------------
// Pass 3: sign accumulator sc = sum(x0 * ||xp0||) per cluster.
// Persistent CTAs; ctr/vd tables in SMEM (128KB) for gathers. The per-point
// atomic is split across pipes: even warps -> SMEM ATOMS histogram (L1),
// odd warps -> replicated global REDG (L2). The two halves overlap.
__global__ void __launch_bounds__(1024, 1)
sc_kernel(const float* __restrict__ data, const int* __restrict__ cid,
          int n, int nquad, int C) {
    extern __shared__ float4 smem[];
    float4* s_ctr = smem;            // [0, C)
    float4* s_vd  = smem + MAXC;     // [MAXC, MAXC+C)
    float*  s_sc  = (float*)(smem + 2 * MAXC);  // C floats

    for (int i = threadIdx.x; i < C; i += blockDim.x) {
        s_ctr[i] = g_ctr[i];
        s_vd[i]  = g_vd[i];
        s_sc[i]  = 0.0f;
    }
    __syncthreads();

    int wid = threadIdx.x >> 5;
    bool use_smem = (wid & 1) == 0;
    int rep = (blockIdx.x * 16 + wid) & (NREP - 1);
    float* sc_rep = g_sc[rep];

    const float4* d4 = (const float4*)data;
    const int4*   c4p = (const int4*)cid;
    int stride = gridDim.x * blockDim.x;

    for (int t = blockIdx.x * blockDim.x + threadIdx.x; t < nquad; t += stride) {
        float4 f0 = d4[t * 5 + 0];
        float4 f1 = d4[t * 5 + 1];
        float4 f2 = d4[t * 5 + 2];
        float4 f3 = d4[t * 5 + 3];
        float4 f4 = d4[t * 5 + 4];
        int4 cc = c4p[t];

        float xs[4] = {f0.x, f1.y, f2.z, f3.w};
        float ys[4] = {f0.y, f1.z, f2.w, f4.x};
        float zs[4] = {f0.z, f1.w, f3.x, f4.y};
        int   cs[4] = {cc.x, cc.y, cc.z, cc.w};

        #pragma unroll
        for (int k = 0; k < 4; k++) {
            int c = cs[k];
            float4 ce = s_ctr[c];
            float4 v  = s_vd[c];
            float xcx = xs[k] - ce.x, xcy = ys[k] - ce.y, xcz = zs[k] - ce.z;
            float x0 = xcx * v.x + xcy * v.y + xcz * v.z;
            float px = xcx - x0 * v.x, py = xcy - x0 * v.y, pz = xcz - x0 * v.z;
            float val = x0 * sqrtf(px * px + py * py + pz * pz);
            if (use_smem) atomicAdd(&s_sc[c], val);        // smem ATOMS (L1)
            else          atomicAdd(&sc_rep[c], val);      // REDG (L2), replicated
        }
    }

    // tail points (n not multiple of 4)
    if (blockIdx.x == 0 && threadIdx.x == 0) {
        for (int i = nquad * 4; i < n; i++) {
            const float* p = data + (size_t)i * 5;
            int c = cid[i];
            float4 ce = s_ctr[c];
            float4 v  = s_vd[c];
            float xcx = p[0] - ce.x, xcy = p[1] - ce.y, xcz = p[2] - ce.z;
            float x0 = xcx * v.x + xcy * v.y + xcz * v.z;
            float px = xcx - x0 * v.x, py = xcy - x0 * v.y, pz = xcz - x0 * v.z;
            atomicAdd(&s_sc[c], x0 * sqrtf(px * px + py * py + pz * pz));
        }
    }
    __syncthreads();

    // flush smem histogram into replica 0
    for (int i = threadIdx.x; i < C; i += blockDim.x) {
        float val = s_sc[i];
        if (val != 0.0f) atomicAdd(&g_sc[0][i], val);
    }
}

// ---------------------------------------------------------------------------
// Pass 4: merge sc replicas (then re-zero), apply sign + dirwt + small mask
__global__ void fin_kernel(float* __restrict__ out, int C) {
    int c = blockIdx.x * blockDim.x + threadIdx.x;
    if (c >= C) return;
    float sc = 0.0f;
    #pragma unroll 8
    for (int r = 0; r < NREP; r++) {
        sc += g_sc[r][c];
        g_sc[r][c] = 0.0f;   // self-clean for next launch
    }
    float4 v = g_vd[c];
    float cnt = g_cnt[c];
    float s = (sc < 0.0f) ? -1.0f : 1.0f;
    float w = (cnt < 2.0f) ? 0.0f : (s * v.w);
    float* o = out + (size_t)c * 16;
    o[12] = v.x * w;
    o[13] = v.y * w;
    o[14] = v.z * w;
}

// ---------------------------------------------------------------------------
extern "C" void kernel_launch(void* const* d_in, const int* in_sizes, int n_in,
                              void* d_out, int out_size) {
    const float* data = (const float*)d_in[0];
    const int*   cid  = (const int*)d_in[1];
    int n = in_sizes[0] / 5;
    int C = out_size / 16;
    if (C > MAXC) C = MAXC;
    float* out = (float*)d_out;

    int nquad = n / 4;
    int blocks = (nquad + 255) / 256;
    moments_kernel<<<blocks, 256>>>(data, cid, n, nquad);
    eig_kernel<<<(C + 127) / 128, 128>>>(out, C);

    int smem_bytes = 2 * MAXC * sizeof(float4) + MAXC * sizeof(float);
    cudaFuncSetAttribute(sc_kernel, cudaFuncAttributeMaxDynamicSharedMemorySize,
                         smem_bytes);
    sc_kernel<<<148, 1024, smem_bytes>>>(data, cid, n, nquad, C);

    fin_kernel<<<(C + 127) / 128, 128>>>(out, C);
}

// round 17
// speedup vs baseline: 1.0827x; 1.0827x over previous
#include <cuda_runtime.h>
#include <math.h>

#define MAXC 4096
#define NREP 16

// Scratch (device globals: zero-initialized at load; every kernel_launch
// leaves them zeroed again -> no standalone zero kernel).
// g_mom[rep][cluster*16]: cnt,sx,sy,sz | sxx,sxy,sxz,syy | syz,szz,pad...
__device__ __align__(128) float g_mom[NREP][MAXC * 16];   // 4 MB
__device__ float4 g_ctr[MAXC];       // cx, cy, cz, 0
__device__ float4 g_vd[MAXC];        // v0x, v0y, v0z, dirwt
__device__ float  g_sc[MAXC];        // sign accumulator
__device__ float  g_cnt[MAXC];       // merged counts (for fin)

// ---------------------------------------------------------------------------
// v4 + v4 + v2 global f32 reductions into one of NREP table replicas.
// (Proven minimum: red.f32 is capped at 128-bit vectors on sm_103.)
__device__ __forceinline__ void mom_red(int rep, int c, float x, float y, float z) {
    float* base = &g_mom[rep][c * 16];
    size_t g0 = __cvta_generic_to_global(base);
    size_t g1 = __cvta_generic_to_global(base + 4);
    size_t g2 = __cvta_generic_to_global(base + 8);
    asm volatile("red.global.add.v4.f32 [%0], {%1,%2,%3,%4};"
                 :: "l"(g0), "f"(1.0f), "f"(x), "f"(y), "f"(z) : "memory");
    asm volatile("red.global.add.v4.f32 [%0], {%1,%2,%3,%4};"
                 :: "l"(g1), "f"(x * x), "f"(x * y), "f"(x * z), "f"(y * y) : "memory");
    asm volatile("red.global.add.v2.f32 [%0], {%1,%2};"
                 :: "l"(g2), "f"(y * z), "f"(z * z) : "memory");
}

// Pass 1: per-cluster moments, 4 records/thread, coalesced LDG.128,
// replica chosen per warp to cut per-address contention 16x.
__global__ void moments_kernel(const float* __restrict__ data,
                               const int* __restrict__ cid, int n, int nquad) {
    int t = blockIdx.x * blockDim.x + threadIdx.x;
    int rep = (blockIdx.x * 8 + (threadIdx.x >> 5)) & (NREP - 1);
    if (t < nquad) {
        const float4* d4 = (const float4*)data;
        float4 f0 = d4[t * 5 + 0];
        float4 f1 = d4[t * 5 + 1];
        float4 f2 = d4[t * 5 + 2];
        float4 f3 = d4[t * 5 + 3];
        float4 f4 = d4[t * 5 + 4];
        int4 c4 = ((const int4*)cid)[t];
        mom_red(rep, c4.x, f0.x, f0.y, f0.z);
        mom_red(rep, c4.y, f1.y, f1.z, f1.w);
        mom_red(rep, c4.z, f2.z, f2.w, f3.x);
        mom_red(rep, c4.w, f3.w, f4.x, f4.y);
    }
    if (t == 0) {
        for (int i = nquad * 4; i < n; i++) {
            const float* p = data + (size_t)i * 5;
            mom_red(0, cid[i], p[0], p[1], p[2]);
        }
    }
}

// ---------------------------------------------------------------------------
// Pass 2: merge replicas (re-zeroing them for the next launch), center,
// cov, analytic 3x3 eigendecomposition (fp64), B = cov / w2, dirwt, v0.
__global__ void eig_kernel(float* __restrict__ out, int C) {
    int c = blockIdx.x * blockDim.x + threadIdx.x;
    if (c >= C) return;

    float s0 = 0, s1 = 0, s2 = 0, s3 = 0, s4 = 0, s5 = 0, s6 = 0, s7 = 0, s8 = 0, s9 = 0;
    const float4 zz = make_float4(0.0f, 0.0f, 0.0f, 0.0f);
    #pragma unroll 4
    for (int r = 0; r < NREP; r++) {
        float4* m4 = (float4*)&g_mom[r][c * 16];
        float4 a = m4[0], b = m4[1], d = m4[2];
        s0 += a.x; s1 += a.y; s2 += a.z; s3 += a.w;
        s4 += b.x; s5 += b.y; s6 += b.z; s7 += b.w;
        s8 += d.x; s9 += d.y;
        m4[0] = zz; m4[1] = zz; m4[2] = zz;   // self-clean for next launch
    }

    float cnt = s0;
    float safe = fmaxf(cnt, 1.0f);
    float cx = s1 / safe, cy = s2 / safe, cz = s3 / safe;

    double dcnt = (double)cnt;
    double a00 = (double)s4 - dcnt * (double)cx * (double)cx;
    double a01 = (double)s5 - dcnt * (double)cx * (double)cy;
    double a02 = (double)s6 - dcnt * (double)cx * (double)cz;
    double a11 = (double)s7 - dcnt * (double)cy * (double)cy;
    double a12 = (double)s8 - dcnt * (double)cy * (double)cz;
    double a22 = (double)s9 - dcnt * (double)cz * (double)cz;

    // eigenvalues (ascending), trig method
    double p1 = a01 * a01 + a02 * a02 + a12 * a12;
    double q  = (a00 + a11 + a22) / 3.0;
    double d0 = a00 - q, d1 = a11 - q, d2 = a22 - q;
    double p2 = d0 * d0 + d1 * d1 + d2 * d2 + 2.0 * p1;
    double w1, w2;
    if (p2 <= 0.0) {
        w1 = w2 = q;
    } else {
        double p = sqrt(p2 / 6.0);
        double ip = 1.0 / p;
        double b00 = d0 * ip, b01 = a01 * ip, b02 = a02 * ip;
        double b11 = d1 * ip, b12 = a12 * ip, b22 = d2 * ip;
        double detB = b00 * (b11 * b22 - b12 * b12)
                    - b01 * (b01 * b22 - b12 * b02)
                    + b02 * (b01 * b12 - b11 * b02);
        double rr = 0.5 * detB;
        rr = fmin(1.0, fmax(-1.0, rr));
        double phi = acos(rr) / 3.0;
        w2 = q + 2.0 * p * cos(phi);
        double w0 = q + 2.0 * p * cos(phi + 2.0943951023931953);
        w1 = 3.0 * q - w0 - w2;
    }

    float dirwt = (w2 > 0.0) ? (float)(1.0 - w1 / w2) : 0.0f;

    // principal eigenvector: cross products of rows of (A - w2*I)
    double m00 = a00 - w2, m11 = a11 - w2, m22 = a22 - w2;
    double c0x = a01 * a12 - a02 * m11, c0y = a02 * a01 - m00 * a12, c0z = m00 * m11 - a01 * a01;
    double c1x = a01 * m22 - a02 * a12, c1y = a02 * a02 - m00 * m22, c1z = m00 * a12 - a01 * a02;
    double c2x = m11 * m22 - a12 * a12, c2y = a12 * a02 - a01 * m22, c2z = a01 * a12 - m11 * a02;
    double n0 = c0x * c0x + c0y * c0y + c0z * c0z;
    double n1 = c1x * c1x + c1y * c1y + c1z * c1z;
    double n2 = c2x * c2x + c2y * c2y + c2z * c2z;
    double vx, vy, vz, nn;
    if (n0 >= n1 && n0 >= n2)      { vx = c0x; vy = c0y; vz = c0z; nn = n0; }
    else if (n1 >= n2)             { vx = c1x; vy = c1y; vz = c1z; nn = n1; }
    else                           { vx = c2x; vy = c2y; vz = c2z; nn = n2; }
    if (nn > 1e-300) {
        double inv = rsqrt(nn);
        vx *= inv; vy *= inv; vz *= inv;
    } else {
        vx = vy = vz = 0.0;
    }

    bool small = cnt < 2.0f;
    double denom = (fabs(w2) > 1e-12) ? w2 : 1.0;
    double ib = 1.0 / denom;

    float* o = out + (size_t)c * 16;
    o[0] = cx; o[1] = cy; o[2] = cz;
    if (small) {
        #pragma unroll
        for (int k = 3; k < 12; k++) o[k] = 0.0f;
    } else {
        o[3]  = (float)(a00 * ib); o[4]  = (float)(a01 * ib); o[5]  = (float)(a02 * ib);
        o[6]  = (float)(a01 * ib); o[7]  = (float)(a11 * ib); o[8]  = (float)(a12 * ib);
        o[9]  = (float)(a02 * ib); o[10] = (float)(a12 * ib); o[11] = (float)(a22 * ib);
    }
    o[15] = cnt;

    g_cnt[c] = cnt;
    g_ctr[c] = make_float4(cx, cy, cz, 0.0f);
    g_vd[c]  = make_float4((float)vx, (float)vy, (float)vz, dirwt);
}

// ---------------------------------------------------------------------------
// Pass 3: sign accumulator sc = sum(x0 * ||xp0||) per cluster.
// Persistent CTAs; ctr/vd tables in SMEM (128KB) + SMEM sc histogram (16KB),
// flushed once per CTA. (Proven 27.5us form — at the smem ATOMS floor.)
__global__ void __launch_bounds__(1024, 1)
sc_kernel(const float* __restrict__ data, const int* __restrict__ cid,
          int n, int nquad, int C) {
    extern __shared__ float4 smem[];
    float4* s_ctr = smem;            // [0, C)
    float4* s_vd  = smem + MAXC;     // [MAXC, MAXC+C)
    float*  s_sc  = (float*)(smem + 2 * MAXC);  // C floats

    for (int i = threadIdx.x; i < C; i += blockDim.x) {
        s_ctr[i] = g_ctr[i];
        s_vd[i]  = g_vd[i];
        s_sc[i]  = 0.0f;
    }
    __syncthreads();

    const float4* d4 = (const float4*)data;
    const int4*   c4p = (const int4*)cid;
    int stride = gridDim.x * blockDim.x;

    for (int t = blockIdx.x * blockDim.x + threadIdx.x; t < nquad; t += stride) {
        float4 f0 = d4[t * 5 + 0];
        float4 f1 = d4[t * 5 + 1];
        float4 f2 = d4[t * 5 + 2];
        float4 f3 = d4[t * 5 + 3];
        float4 f4 = d4[t * 5 + 4];
        int4 cc = c4p[t];

        float xs[4] = {f0.x, f1.y, f2.z, f3.w};
        float ys[4] = {f0.y, f1.z, f2.w, f4.x};
        float zs[4] = {f0.z, f1.w, f3.x, f4.y};
        int   cs[4] = {cc.x, cc.y, cc.z, cc.w};

        #pragma unroll
        for (int k = 0; k < 4; k++) {
            int c = cs[k];
            float4 ce = s_ctr[c];
            float4 v  = s_vd[c];
            float xcx = xs[k] - ce.x, xcy = ys[k] - ce.y, xcz = zs[k] - ce.z;
            float x0 = xcx * v.x + xcy * v.y + xcz * v.z;
            float px = xcx - x0 * v.x, py = xcy - x0 * v.y, pz = xcz - x0 * v.z;
            float np0 = sqrtf(px * px + py * py + pz * pz);
            atomicAdd(&s_sc[c], x0 * np0);
        }
    }

    // tail points (n not multiple of 4)
    if (blockIdx.x == 0 && threadIdx.x == 0) {
        for (int i = nquad * 4; i < n; i++) {
            const float* p = data + (size_t)i * 5;
            int c = cid[i];
            float4 ce = s_ctr[c];
            float4 v  = s_vd[c];
            float xcx = p[0] - ce.x, xcy = p[1] - ce.y, xcz = p[2] - ce.z;
            float x0 = xcx * v.x + xcy * v.y + xcz * v.z;
            float px = xcx - x0 * v.x, py = xcy - x0 * v.y, pz = xcz - x0 * v.z;
            atomicAdd(&s_sc[c], x0 * sqrtf(px * px + py * py + pz * pz));
        }
    }
    __syncthreads();

    for (int i = threadIdx.x; i < C; i += blockDim.x) {
        float val = s_sc[i];
        if (val != 0.0f) atomicAdd(&g_sc[i], val);
    }
}

// ---------------------------------------------------------------------------
// Pass 4: apply sign + dirwt + small-cluster mask to v0; self-clean g_sc.
__global__ void fin_kernel(float* __restrict__ out, int C) {
    int c = blockIdx.x * blockDim.x + threadIdx.x;
    if (c >= C) return;
    float4 v = g_vd[c];
    float sc = g_sc[c];
    g_sc[c] = 0.0f;   // self-clean for next launch
    float cnt = g_cnt[c];
    float s = (sc < 0.0f) ? -1.0f : 1.0f;
    float w = (cnt < 2.0f) ? 0.0f : (s * v.w);
    float* o = out + (size_t)c * 16;
    o[12] = v.x * w;
    o[13] = v.y * w;
    o[14] = v.z * w;
}

// ---------------------------------------------------------------------------
extern "C" void kernel_launch(void* const* d_in, const int* in_sizes, int n_in,
                              void* d_out, int out_size) {
    const float* data = (const float*)d_in[0];
    const int*   cid  = (const int*)d_in[1];
    int n = in_sizes[0] / 5;
    int C = out_size / 16;
    if (C > MAXC) C = MAXC;
    float* out = (float*)d_out;

    int nquad = n / 4;
    int blocks = (nquad + 255) / 256;
    moments_kernel<<<blocks, 256>>>(data, cid, n, nquad);
    eig_kernel<<<(C + 127) / 128, 128>>>(out, C);

    int smem_bytes = 2 * MAXC * sizeof(float4) + MAXC * sizeof(float);
    cudaFuncSetAttribute(sc_kernel, cudaFuncAttributeMaxDynamicSharedMemorySize,
                         smem_bytes);
    sc_kernel<<<148, 1024, smem_bytes>>>(data, cid, n, nquad, C);

    fin_kernel<<<(C + 127) / 128, 128>>>(out, C);
}